// round 2
// baseline (speedup 1.0000x reference)
#include <cuda_runtime.h>

#define GB 16
#define NN 1024
#define DD 8
#define FIN 128
#define FF 64

// ---------------- scratch (static device globals; no allocation) ----------------
static __device__ float g_h[GB*NN*FF];            // 4 MB
static __device__ float g_src[GB*NN];
static __device__ float g_dst[GB*NN];
static __device__ unsigned short g_uniq[GB*NN*DD];
static __device__ int g_ucnt[GB*NN];
static __device__ unsigned int g_a2[GB*NN*64];    // packed: idx | (count<<16), nnz<=64
static __device__ int g_a2cnt[GB*NN];
static __device__ float g_blend[(size_t)GB*NN*NN];// 64 MB
static __device__ int g_is64;

// ---------------- f32x2 helpers ----------------
__device__ __forceinline__ unsigned long long pk2(float x, float y) {
    unsigned long long r;
    asm("mov.b64 %0, {%1,%2};" : "=l"(r) : "f"(x), "f"(y));
    return r;
}
__device__ __forceinline__ unsigned long long ffma2(unsigned long long a,
                                                    unsigned long long b,
                                                    unsigned long long c) {
    unsigned long long d;
    asm("fma.rn.f32x2 %0, %1, %2, %3;" : "=l"(d) : "l"(a), "l"(b), "l"(c));
    return d;
}
__device__ __forceinline__ float2 upk2(unsigned long long v) {
    float2 r;
    asm("mov.b64 {%0,%1}, %2;" : "=f"(r.x), "=f"(r.y) : "l"(v));
    return r;
}

// ---------------- K0: detect int32 vs int64 edges ----------------
__global__ void k_detect(const int* __restrict__ edges) {
    // If edges is int64 little-endian with values in [0,1024), every odd 32-bit
    // word of the first 8 words is 0. For random int32 data P(false positive) ~ 1e-12.
    g_is64 = (edges[1] == 0 && edges[3] == 0 && edges[5] == 0 && edges[7] == 0) ? 1 : 0;
}

// ---------------- K1: h = atoms @ W, src = h@a1, dst = h@a2 ----------------
__global__ __launch_bounds__(128) void k_h(const float* __restrict__ atoms,
                                           const float* __restrict__ W,
                                           const float* __restrict__ a) {
    const int i = blockIdx.x, g = blockIdx.y;
    const int row = g * NN + i;
    __shared__ float sa[FIN];
    __shared__ float r1[64], r2[64];
    const int tid = threadIdx.x;
    sa[tid] = atoms[(size_t)row * FIN + tid];
    __syncthreads();
    float hv = 0.f;
    if (tid < FF) {
        float acc = 0.f;
        #pragma unroll 16
        for (int k = 0; k < FIN; k++) acc += sa[k] * __ldg(&W[k * FF + tid]);
        g_h[(size_t)row * FF + tid] = acc;
        hv = acc;
        r1[tid] = hv * __ldg(&a[tid]);
        r2[tid] = hv * __ldg(&a[FF + tid]);
    }
    __syncthreads();
    for (int s = 32; s > 0; s >>= 1) {
        if (tid < s) { r1[tid] += r1[tid + s]; r2[tid] += r2[tid + s]; }
        __syncthreads();
    }
    if (tid == 0) { g_src[row] = r1[0]; g_dst[row] = r2[0]; }
}

// ---------------- K2a: unique neighbor lists ----------------
__global__ __launch_bounds__(256) void k_uniq(const int* __restrict__ edges) {
    const int row = blockIdx.x * 256 + threadIdx.x;
    if (row >= GB * NN) return;
    const int is64 = g_is64;
    int e[DD];
    #pragma unroll
    for (int d = 0; d < DD; d++) {
        int w = is64 ? edges[(size_t)(row * DD + d) * 2] : edges[row * DD + d];
        e[d] = w & (NN - 1);
    }
    unsigned short u[DD]; int c = 0;
    #pragma unroll
    for (int d = 0; d < DD; d++) {
        bool dup = false;
        for (int t = 0; t < c; t++) if (u[t] == (unsigned short)e[d]) dup = true;
        if (!dup) u[c++] = (unsigned short)e[d];
    }
    g_ucnt[row] = c;
    #pragma unroll
    for (int d = 0; d < DD; d++) g_uniq[row * DD + d] = (d < c) ? u[d] : 0;
}

// ---------------- K2b: sparse A^2 rows ----------------
__global__ __launch_bounds__(64) void k_a2(void) {
    const int i = blockIdx.x, g = blockIdx.y;
    const int row = g * NN + i;
    __shared__ unsigned int cnt[NN];
    __shared__ int nnz;
    const int tid = threadIdx.x;
    for (int t = tid; t < NN; t += 64) cnt[t] = 0;
    if (tid == 0) nnz = 0;
    __syncthreads();
    const int uc = g_ucnt[row];
    const int d = tid >> 3, e2 = tid & 7;
    if (d < uc) {
        const int k = g_uniq[row * DD + d];
        const int krow = g * NN + k;
        if (e2 < g_ucnt[krow]) {
            const int j = g_uniq[krow * DD + e2];
            atomicAdd(&cnt[j], 1u);
        }
    }
    __syncthreads();
    for (int t = tid; t < NN; t += 64) {
        const unsigned c = cnt[t];
        if (c) {
            const int p = atomicAdd(&nnz, 1);
            g_a2[row * 64 + p] = (unsigned)t | (c << 16);
        }
    }
    __syncthreads();
    if (tid == 0) g_a2cnt[row] = nnz;
}

// ---------------- K3: dense blended row = 0.5*att + 0.5*softmax(A+A^2+A^3) ----------------
__global__ __launch_bounds__(256) void k_blend(void) {
    const int i = blockIdx.x, g = blockIdx.y;
    const int row = g * NN + i;
    __shared__ float acc[NN];
    __shared__ float red[256];
    __shared__ unsigned short su[DD];
    __shared__ int sucnt;
    __shared__ float attw[DD];
    const int tid = threadIdx.x;
    float4* acc4 = (float4*)acc;
    acc4[tid] = make_float4(0.f, 0.f, 0.f, 0.f);
    if (tid == 0) sucnt = g_ucnt[row];
    if (tid < DD) su[tid] = g_uniq[row * DD + tid];
    __syncthreads();
    const int uc = sucnt;
    // A contribution (unique -> distinct indices, but keep atomics: cheap & safe)
    if (tid < uc) atomicAdd(&acc[su[tid]], 1.0f);
    // A^2 (self row)
    if (tid >= 64 && tid < 128) {
        const int t = tid - 64;
        if (t < g_a2cnt[row]) {
            const unsigned e = g_a2[row * 64 + t];
            atomicAdd(&acc[e & 0xFFFFu], (float)(e >> 16));
        }
    }
    // A^3 = sum over neighbors k of A^2[k,:]
    for (int w = tid; w < uc * 64; w += 256) {
        const int d = w >> 6, t = w & 63;
        const int krow = g * NN + su[d];
        if (t < g_a2cnt[krow]) {
            const unsigned e = g_a2[krow * 64 + t];
            atomicAdd(&acc[e & 0xFFFFu], (float)(e >> 16));
        }
    }
    __syncthreads();
    // row max (all counts >= 0)
    float4 v = acc4[tid];
    float m = fmaxf(fmaxf(v.x, v.y), fmaxf(v.z, v.w));
    red[tid] = m; __syncthreads();
    for (int s = 128; s > 0; s >>= 1) {
        if (tid < s) red[tid] = fmaxf(red[tid], red[tid + s]);
        __syncthreads();
    }
    const float mx = red[0];
    __syncthreads();
    // exp + sum
    v.x = __expf(v.x - mx); v.y = __expf(v.y - mx);
    v.z = __expf(v.z - mx); v.w = __expf(v.w - mx);
    acc4[tid] = v;
    red[tid] = (v.x + v.y) + (v.z + v.w); __syncthreads();
    for (int s = 128; s > 0; s >>= 1) {
        if (tid < s) red[tid] += red[tid + s];
        __syncthreads();
    }
    const float invZ = 0.5f / red[0];   // fold RATIO=0.5
    // attention over unique neighbors (sparse softmax; other entries exp->0 exactly)
    if (tid == 0) {
        const float s0 = g_src[row];
        float ev[DD]; float me = -1e30f;
        for (int d = 0; d < uc; d++) {
            float x = s0 + g_dst[g * NN + su[d]];
            x = (x > 0.f) ? x : 0.2f * x;           // leaky_relu
            ev[d] = x; me = fmaxf(me, x);
        }
        float Z = 0.f;
        for (int d = 0; d < uc; d++) { ev[d] = __expf(ev[d] - me); Z += ev[d]; }
        const float iz = 0.5f / Z;
        for (int d = 0; d < uc; d++) attw[d] = ev[d] * iz;
    }
    __syncthreads();
    // scale structure part
    v = acc4[tid];
    v.x *= invZ; v.y *= invZ; v.z *= invZ; v.w *= invZ;
    acc4[tid] = v;
    __syncthreads();
    if (tid < uc) acc[su[tid]] += attw[tid];        // distinct indices
    __syncthreads();
    float4* out4 = (float4*)(g_blend + (size_t)row * NN);
    out4[tid] = acc4[tid];
}

// ---------------- K4: out = elu(blended @ h), batched [1024x1024]@[1024x64] ----------------
__global__ __launch_bounds__(256) void k_gemm(float* __restrict__ out) {
    const int g = blockIdx.y;
    const int i0 = blockIdx.x * 64;
    __shared__ float As[32][68];   // As[k][i] transposed, padded
    __shared__ float Bs[32][64];
    const int tid = threadIdx.x;
    const int tx = tid & 15, ty = tid >> 4;
    unsigned long long acc[4][2];
    #pragma unroll
    for (int m = 0; m < 4; m++) { acc[m][0] = 0ull; acc[m][1] = 0ull; }
    const float* Abase = g_blend + ((size_t)g * NN + i0) * NN;
    const float* Bbase = g_h + (size_t)g * NN * FF;
    for (int k0 = 0; k0 < NN; k0 += 32) {
        #pragma unroll
        for (int p = 0; p < 2; p++) {
            const int idx = p * 256 + tid;
            const int r = idx >> 3, q = idx & 7;
            const float4 va = *(const float4*)(Abase + (size_t)r * NN + k0 + q * 4);
            As[q * 4 + 0][r] = va.x; As[q * 4 + 1][r] = va.y;
            As[q * 4 + 2][r] = va.z; As[q * 4 + 3][r] = va.w;
        }
        #pragma unroll
        for (int p = 0; p < 2; p++) {
            const int idx = p * 256 + tid;
            const int r = idx >> 4, q = idx & 15;
            *(float4*)&Bs[r][q * 4] = *(const float4*)(Bbase + (size_t)(k0 + r) * FF + q * 4);
        }
        __syncthreads();
        #pragma unroll
        for (int k = 0; k < 32; k++) {
            const float4 b4 = *(const float4*)&Bs[k][tx * 4];
            const unsigned long long b01 = pk2(b4.x, b4.y);
            const unsigned long long b23 = pk2(b4.z, b4.w);
            const float4 a4 = *(const float4*)&As[k][ty * 4];
            const float av[4] = {a4.x, a4.y, a4.z, a4.w};
            #pragma unroll
            for (int m = 0; m < 4; m++) {
                const unsigned long long ap = pk2(av[m], av[m]);
                acc[m][0] = ffma2(ap, b01, acc[m][0]);
                acc[m][1] = ffma2(ap, b23, acc[m][1]);
            }
        }
        __syncthreads();
    }
    #pragma unroll
    for (int m = 0; m < 4; m++) {
        const float2 v0 = upk2(acc[m][0]);
        const float2 v1 = upk2(acc[m][1]);
        float4 o;
        o.x = (v0.x > 0.f) ? v0.x : (expf(v0.x) - 1.f);
        o.y = (v0.y > 0.f) ? v0.y : (expf(v0.y) - 1.f);
        o.z = (v1.x > 0.f) ? v1.x : (expf(v1.x) - 1.f);
        o.w = (v1.y > 0.f) ? v1.y : (expf(v1.y) - 1.f);
        const int row = i0 + ty * 4 + m;
        *(float4*)(out + ((size_t)g * NN + row) * FF + tx * 4) = o;
    }
}

// ---------------- launcher ----------------
extern "C" void kernel_launch(void* const* d_in, const int* in_sizes, int n_in,
                              void* d_out, int out_size) {
    const float* atoms = (const float*)d_in[0];
    const int*   edges = (const int*)d_in[1];
    const float* W     = (const float*)d_in[2];
    const float* a     = (const float*)d_in[3];
    float* out = (float*)d_out;
    (void)in_sizes; (void)n_in; (void)out_size;

    dim3 gnb(NN, GB);
    k_detect<<<1, 1>>>(edges);
    k_h<<<gnb, 128>>>(atoms, W, a);
    k_uniq<<<(GB * NN + 255) / 256, 256>>>(edges);
    k_a2<<<gnb, 64>>>();
    k_blend<<<gnb, 256>>>();
    k_gemm<<<dim3(NN / 64, GB), 256>>>(out);
}

// round 3
// speedup vs baseline: 1.2362x; 1.2362x over previous
#include <cuda_runtime.h>

#define GB 16
#define NN 1024
#define DD 8
#define FIN 128
#define FF 64
#define INVID 0xFFFFu

// ---------------- scratch (static device globals; no allocation) ----------------
static __device__ float g_h[GB*NN*FF];                         // 4 MB
static __device__ float g_src[GB*NN];
static __device__ float g_dst[GB*NN];
static __device__ __align__(16) unsigned short g_uniq[GB*NN*DD];
static __device__ float g_blend[(size_t)GB*NN*NN];             // 64 MB (L2-resident)

// ---------------- f32x2 helpers ----------------
__device__ __forceinline__ unsigned long long pk2(float x, float y) {
    unsigned long long r;
    asm("mov.b64 %0, {%1,%2};" : "=l"(r) : "f"(x), "f"(y));
    return r;
}
__device__ __forceinline__ unsigned long long ffma2(unsigned long long a,
                                                    unsigned long long b,
                                                    unsigned long long c) {
    unsigned long long d;
    asm("fma.rn.f32x2 %0, %1, %2, %3;" : "=l"(d) : "l"(a), "l"(b), "l"(c));
    return d;
}
__device__ __forceinline__ float2 upk2(unsigned long long v) {
    float2 r;
    asm("mov.b64 {%0,%1}, %2;" : "=f"(r.x), "=f"(r.y) : "l"(v));
    return r;
}

// ---------------- K1: unique neighbor lists with 0xFFFF sentinels ----------------
__global__ __launch_bounds__(256) void k_uniq(const int* __restrict__ edges) {
    const int row = blockIdx.x * 256 + threadIdx.x;
    if (row >= GB * NN) return;
    // int64 edges little-endian with values <1024 -> odd words of first 8 are 0.
    const bool is64 = (edges[1] == 0) && (edges[3] == 0) && (edges[5] == 0) && (edges[7] == 0);
    unsigned e[DD];
    #pragma unroll
    for (int d = 0; d < DD; d++) {
        int w = is64 ? edges[((size_t)row * DD + d) * 2] : edges[row * DD + d];
        e[d] = (unsigned)w & (NN - 1);
    }
    unsigned u[DD];
    int c = 0;
    #pragma unroll
    for (int d = 0; d < DD; d++) {
        bool dup = false;
        #pragma unroll
        for (int t2 = 0; t2 < DD; t2++) if (t2 < c && u[t2] == e[d]) dup = true;
        if (!dup) u[c++] = e[d];
    }
    #pragma unroll
    for (int d = 0; d < DD; d++) if (d >= c) u[d] = INVID;
    uint4 pk;
    pk.x = u[0] | (u[1] << 16);
    pk.y = u[2] | (u[3] << 16);
    pk.z = u[4] | (u[5] << 16);
    pk.w = u[6] | (u[7] << 16);
    ((uint4*)g_uniq)[row] = pk;
}

// ---------------- K2: h = atoms @ W (tiled GEMM) + src/dst fused ----------------
__global__ __launch_bounds__(256) void k_h(const float* __restrict__ atoms,
                                           const float* __restrict__ W,
                                           const float* __restrict__ a) {
    const int g = blockIdx.y, i0 = blockIdx.x * 64;
    __shared__ float sAT[64][68];      // [k][row], transposed, padded
    __shared__ float sW[64][64];       // [k][col]
    __shared__ float ssrc[64], sdst[64];
    const int tid = threadIdx.x, tx = tid & 15, ty = tid >> 4;
    float acc[4][4];
    #pragma unroll
    for (int r = 0; r < 4; r++)
        #pragma unroll
        for (int c = 0; c < 4; c++) acc[r][c] = 0.f;

    const float* Ab = atoms + ((size_t)(g * NN + i0)) * FIN;
    for (int ks = 0; ks < 2; ks++) {
        #pragma unroll
        for (int p = 0; p < 4; p++) {
            const int idx = p * 256 + tid;
            const int r = idx >> 4, q = idx & 15;
            const float4 va = *(const float4*)(Ab + (size_t)r * FIN + ks * 64 + q * 4);
            sAT[q * 4 + 0][r] = va.x; sAT[q * 4 + 1][r] = va.y;
            sAT[q * 4 + 2][r] = va.z; sAT[q * 4 + 3][r] = va.w;
        }
        #pragma unroll
        for (int p = 0; p < 4; p++) {
            const int idx = p * 256 + tid;
            const int k = idx >> 4, c = (idx & 15) * 4;
            *(float4*)&sW[k][c] = *(const float4*)(W + (size_t)(ks * 64 + k) * FF + c);
        }
        __syncthreads();
        #pragma unroll 8
        for (int k = 0; k < 64; k++) {
            const float4 a4 = *(const float4*)&sAT[k][ty * 4];
            const float4 b4 = *(const float4*)&sW[k][tx * 4];
            const float av[4] = {a4.x, a4.y, a4.z, a4.w};
            const float bv[4] = {b4.x, b4.y, b4.z, b4.w};
            #pragma unroll
            for (int r = 0; r < 4; r++)
                #pragma unroll
                for (int c = 0; c < 4; c++) acc[r][c] += av[r] * bv[c];
        }
        __syncthreads();
    }
    // epilogue: store h, deterministic 16-lane shuffle reductions for src/dst
    float a1v[4], a2v[4];
    #pragma unroll
    for (int j = 0; j < 4; j++) { a1v[j] = a[tx * 4 + j]; a2v[j] = a[FF + tx * 4 + j]; }
    #pragma unroll
    for (int r = 0; r < 4; r++) {
        float4 o;
        o.x = acc[r][0]; o.y = acc[r][1]; o.z = acc[r][2]; o.w = acc[r][3];
        *(float4*)(g_h + ((size_t)(g * NN + i0 + ty * 4 + r)) * FF + tx * 4) = o;
        float sr = acc[r][0] * a1v[0] + acc[r][1] * a1v[1] + acc[r][2] * a1v[2] + acc[r][3] * a1v[3];
        float sd = acc[r][0] * a2v[0] + acc[r][1] * a2v[1] + acc[r][2] * a2v[2] + acc[r][3] * a2v[3];
        // threads sharing a row are the 16 consecutive lanes of a half-warp
        #pragma unroll
        for (int off = 8; off > 0; off >>= 1) {
            sr += __shfl_xor_sync(0xFFFFFFFFu, sr, off);
            sd += __shfl_xor_sync(0xFFFFFFFFu, sd, off);
        }
        if (tx == 0) { ssrc[ty * 4 + r] = sr; sdst[ty * 4 + r] = sd; }
    }
    __syncthreads();
    if (tid < 64) {
        g_src[g * NN + i0 + tid] = ssrc[tid];
        g_dst[g * NN + i0 + tid] = sdst[tid];
    }
}

// ---------------- K3: blended rows via direct A/A^2/A^3 traversal ----------------
__global__ __launch_bounds__(256) void k_blend(void) {
    const int g = blockIdx.y, rbase = blockIdx.x * 32;
    __shared__ unsigned short tbl[NN * DD];   // 16 KB: whole graph's neighbor table
    __shared__ float acc[NN];
    __shared__ float sredm[8], sreds[8], attw[8];
    const int t = threadIdx.x, w = t >> 5, lane = t & 31;

    {   // load neighbor table for this graph
        const uint4* src = (const uint4*)(g_uniq + (size_t)g * NN * DD);
        uint4* dst = (uint4*)tbl;
        #pragma unroll
        for (int p = 0; p < 4; p++) dst[p * 256 + t] = src[p * 256 + t];
    }
    float4* acc4 = (float4*)acc;
    acc4[t] = make_float4(0.f, 0.f, 0.f, 0.f);
    __syncthreads();

    for (int r = 0; r < 32; r++) {
        const int i = rbase + r;
        const unsigned short* ti = &tbl[i * DD];
        // ---- scatter counts for A, A^2, A^3 (+ attention weights on warp0 lanes 0..7)
        if (t < 8) {
            const unsigned j = ti[t];
            if (j != INVID) atomicAdd(&acc[j], 1.0f);
            // attention over unique neighbors (all other entries exp -> exactly 0)
            float x = -3.0e38f;
            const bool valid = (j != INVID);
            if (valid) {
                const float v = g_src[g * NN + i] + g_dst[g * NN + j];
                x = (v > 0.f) ? v : 0.2f * v;          // leaky_relu
            }
            float me = x;
            #pragma unroll
            for (int off = 4; off > 0; off >>= 1) me = fmaxf(me, __shfl_xor_sync(0xFFu, me, off));
            const float ev = valid ? __expf(x - me) : 0.f;
            float Za = ev;
            #pragma unroll
            for (int off = 4; off > 0; off >>= 1) Za += __shfl_xor_sync(0xFFu, Za, off);
            attw[t] = valid ? (0.5f * ev / Za) : 0.f;
        }
        if (t < 64) {
            const int d = t >> 3, e = t & 7;
            const unsigned k = ti[d];
            if (k != INVID) {
                const unsigned j = tbl[k * DD + e];
                if (j != INVID) atomicAdd(&acc[j], 1.0f);
            }
        }
        for (int ww = t; ww < 512; ww += 256) {
            const int d = ww >> 6, e = (ww >> 3) & 7, f = ww & 7;
            const unsigned k = ti[d];
            if (k == INVID) continue;
            const unsigned m = tbl[k * DD + e];
            if (m == INVID) continue;
            const unsigned j = tbl[m * DD + f];
            if (j != INVID) atomicAdd(&acc[j], 1.0f);
        }
        __syncthreads();
        // ---- row softmax of counts
        float4 v = acc4[t];
        float mm = fmaxf(fmaxf(v.x, v.y), fmaxf(v.z, v.w));
        #pragma unroll
        for (int off = 16; off > 0; off >>= 1) mm = fmaxf(mm, __shfl_xor_sync(0xFFFFFFFFu, mm, off));
        if (lane == 0) sredm[w] = mm;
        __syncthreads();
        float mx = sredm[0];
        #pragma unroll
        for (int q = 1; q < 8; q++) mx = fmaxf(mx, sredm[q]);
        v.x = __expf(v.x - mx); v.y = __expf(v.y - mx);
        v.z = __expf(v.z - mx); v.w = __expf(v.w - mx);
        acc4[t] = v;
        float ss = (v.x + v.y) + (v.z + v.w);
        #pragma unroll
        for (int off = 16; off > 0; off >>= 1) ss += __shfl_xor_sync(0xFFFFFFFFu, ss, off);
        if (lane == 0) sreds[w] = ss;
        __syncthreads();
        float Z = 0.f;
        #pragma unroll
        for (int q = 0; q < 8; q++) Z += sreds[q];
        // add attention pre-scaled so the final *invZ recovers attw exactly (to 1 ulp)
        if (t < 8) {
            const unsigned j = ti[t];
            if (j != INVID) atomicAdd(&acc[j], attw[t] * (2.0f * Z));
        }
        __syncthreads();
        const float invZ = 0.5f / Z;
        float4 o = acc4[t];
        o.x *= invZ; o.y *= invZ; o.z *= invZ; o.w *= invZ;
        ((float4*)(g_blend + ((size_t)(g * NN + i)) * NN))[t] = o;
        acc4[t] = make_float4(0.f, 0.f, 0.f, 0.f);   // own elements only: safe
        __syncthreads();
    }
}

// ---------------- K4: out = elu(blend @ h), 128x64 tile, 8x8/thread, FFMA2 ----------------
__global__ __launch_bounds__(128) void k_gemm(float* __restrict__ out) {
    const int g = blockIdx.y, i0 = blockIdx.x * 128;
    __shared__ float As[2][16][132];   // [buf][k][row]
    __shared__ float Bs[2][16][68];    // [buf][k][col]
    const int tid = threadIdx.x, tx = tid & 7, ty = tid >> 3;
    unsigned long long acc[8][4];
    #pragma unroll
    for (int m = 0; m < 8; m++)
        #pragma unroll
        for (int c = 0; c < 4; c++) acc[m][c] = 0ull;

    const float* Ab = g_blend + ((size_t)(g * NN + i0)) * NN;
    const float* Bb = g_h + (size_t)g * NN * FF;
    float4 ra[4], rb[2];
    // prologue: load tile 0
    #pragma unroll
    for (int p = 0; p < 4; p++) {
        const int idx = p * 128 + tid, rr = idx >> 2, q = idx & 3;
        ra[p] = *(const float4*)(Ab + (size_t)rr * NN + q * 4);
    }
    #pragma unroll
    for (int p = 0; p < 2; p++) {
        const int idx = p * 128 + tid, rr = idx >> 4, c = (idx & 15) * 4;
        rb[p] = *(const float4*)(Bb + (size_t)rr * FF + c);
    }
    #pragma unroll
    for (int p = 0; p < 4; p++) {
        const int idx = p * 128 + tid, rr = idx >> 2, q = idx & 3;
        As[0][q * 4 + 0][rr] = ra[p].x; As[0][q * 4 + 1][rr] = ra[p].y;
        As[0][q * 4 + 2][rr] = ra[p].z; As[0][q * 4 + 3][rr] = ra[p].w;
    }
    #pragma unroll
    for (int p = 0; p < 2; p++) {
        const int idx = p * 128 + tid, rr = idx >> 4, c = (idx & 15) * 4;
        *(float4*)&Bs[0][rr][c] = rb[p];
    }
    __syncthreads();

    for (int ks = 0; ks < 64; ks++) {
        const int buf = ks & 1;
        if (ks < 63) {
            const int k0 = (ks + 1) * 16;
            #pragma unroll
            for (int p = 0; p < 4; p++) {
                const int idx = p * 128 + tid, rr = idx >> 2, q = idx & 3;
                ra[p] = *(const float4*)(Ab + (size_t)rr * NN + k0 + q * 4);
            }
            #pragma unroll
            for (int p = 0; p < 2; p++) {
                const int idx = p * 128 + tid, rr = idx >> 4, c = (idx & 15) * 4;
                rb[p] = *(const float4*)(Bb + (size_t)(k0 + rr) * FF + c);
            }
        }
        #pragma unroll
        for (int k = 0; k < 16; k++) {
            const float4 a0 = *(const float4*)&As[buf][k][ty * 8];
            const float4 a1 = *(const float4*)&As[buf][k][ty * 8 + 4];
            const float4 b0 = *(const float4*)&Bs[buf][k][tx * 8];
            const float4 b1 = *(const float4*)&Bs[buf][k][tx * 8 + 4];
            const unsigned long long bp0 = pk2(b0.x, b0.y), bp1 = pk2(b0.z, b0.w);
            const unsigned long long bp2 = pk2(b1.x, b1.y), bp3 = pk2(b1.z, b1.w);
            const float av[8] = {a0.x, a0.y, a0.z, a0.w, a1.x, a1.y, a1.z, a1.w};
            #pragma unroll
            for (int m = 0; m < 8; m++) {
                const unsigned long long ap = pk2(av[m], av[m]);
                acc[m][0] = ffma2(ap, bp0, acc[m][0]);
                acc[m][1] = ffma2(ap, bp1, acc[m][1]);
                acc[m][2] = ffma2(ap, bp2, acc[m][2]);
                acc[m][3] = ffma2(ap, bp3, acc[m][3]);
            }
        }
        if (ks < 63) {
            const int nb = buf ^ 1;
            #pragma unroll
            for (int p = 0; p < 4; p++) {
                const int idx = p * 128 + tid, rr = idx >> 2, q = idx & 3;
                As[nb][q * 4 + 0][rr] = ra[p].x; As[nb][q * 4 + 1][rr] = ra[p].y;
                As[nb][q * 4 + 2][rr] = ra[p].z; As[nb][q * 4 + 3][rr] = ra[p].w;
            }
            #pragma unroll
            for (int p = 0; p < 2; p++) {
                const int idx = p * 128 + tid, rr = idx >> 4, c = (idx & 15) * 4;
                *(float4*)&Bs[nb][rr][c] = rb[p];
            }
        }
        __syncthreads();
    }
    // epilogue: ELU + store
    #pragma unroll
    for (int m = 0; m < 8; m++) {
        const float2 v0 = upk2(acc[m][0]), v1 = upk2(acc[m][1]);
        const float2 v2 = upk2(acc[m][2]), v3 = upk2(acc[m][3]);
        float o[8] = {v0.x, v0.y, v1.x, v1.y, v2.x, v2.y, v3.x, v3.y};
        #pragma unroll
        for (int q = 0; q < 8; q++) o[q] = (o[q] > 0.f) ? o[q] : (__expf(o[q]) - 1.f);
        const int row = i0 + ty * 8 + m;
        float4 w0, w1;
        w0.x = o[0]; w0.y = o[1]; w0.z = o[2]; w0.w = o[3];
        w1.x = o[4]; w1.y = o[5]; w1.z = o[6]; w1.w = o[7];
        float* op = out + ((size_t)(g * NN + row)) * FF + tx * 8;
        *(float4*)op = w0;
        *(float4*)(op + 4) = w1;
    }
}

// ---------------- launcher ----------------
extern "C" void kernel_launch(void* const* d_in, const int* in_sizes, int n_in,
                              void* d_out, int out_size) {
    const float* atoms = (const float*)d_in[0];
    const int*   edges = (const int*)d_in[1];
    const float* W     = (const float*)d_in[2];
    const float* a     = (const float*)d_in[3];
    float* out = (float*)d_out;
    (void)in_sizes; (void)n_in; (void)out_size;

    k_h<<<dim3(16, GB), 256>>>(atoms, W, a);
    k_uniq<<<(GB * NN) / 256, 256>>>(edges);
    k_blend<<<dim3(32, GB), 256>>>();
    k_gemm<<<dim3(8, GB), 128>>>(out);
}

// round 7
// speedup vs baseline: 1.3109x; 1.0605x over previous
#include <cuda_runtime.h>

#define GB 16
#define NN 1024
#define DD 8
#define FIN 128
#define FF 64
#define INVID 0xFFFFu

// ---------------- scratch (static device globals; no allocation) ----------------
static __device__ float g_h[GB*NN*FF];                         // 4 MB
static __device__ float g_src[GB*NN];
static __device__ float g_dst[GB*NN];
static __device__ __align__(16) unsigned short g_uniq[GB*NN*DD];
static __device__ float g_blend[(size_t)GB*NN*NN];             // 64 MB (L2-resident)

// ---------------- f32x2 helpers ----------------
__device__ __forceinline__ unsigned long long ffma2(unsigned long long a,
                                                    unsigned long long b,
                                                    unsigned long long c) {
    unsigned long long d;
    asm("fma.rn.f32x2 %0, %1, %2, %3;" : "=l"(d) : "l"(a), "l"(b), "l"(c));
    return d;
}
__device__ __forceinline__ float2 upk2(unsigned long long v) {
    float2 r;
    asm("mov.b64 {%0,%1}, %2;" : "=f"(r.x), "=f"(r.y) : "l"(v));
    return r;
}

// ---------------- K1: unique neighbor lists with 0xFFFF sentinels ----------------
__global__ __launch_bounds__(256) void k_uniq(const int* __restrict__ edges) {
    const int row = blockIdx.x * 256 + threadIdx.x;
    if (row >= GB * NN) return;
    // int64 edges little-endian with values <1024 -> odd words of first 8 are 0.
    const bool is64 = (edges[1] == 0) && (edges[3] == 0) && (edges[5] == 0) && (edges[7] == 0);
    unsigned e[DD];
    #pragma unroll
    for (int d = 0; d < DD; d++) {
        int w = is64 ? edges[((size_t)row * DD + d) * 2] : edges[row * DD + d];
        e[d] = (unsigned)w & (NN - 1);
    }
    unsigned u[DD];
    int c = 0;
    #pragma unroll
    for (int d = 0; d < DD; d++) {
        bool dup = false;
        #pragma unroll
        for (int t2 = 0; t2 < DD; t2++) if (t2 < c && u[t2] == e[d]) dup = true;
        if (!dup) u[c++] = e[d];
    }
    #pragma unroll
    for (int d = 0; d < DD; d++) if (d >= c) u[d] = INVID;
    uint4 pk;
    pk.x = u[0] | (u[1] << 16);
    pk.y = u[2] | (u[3] << 16);
    pk.z = u[4] | (u[5] << 16);
    pk.w = u[6] | (u[7] << 16);
    ((uint4*)g_uniq)[row] = pk;
}

// ---------------- K2: h = atoms @ W (tiled GEMM) + src/dst fused ----------------
__global__ __launch_bounds__(256) void k_h(const float* __restrict__ atoms,
                                           const float* __restrict__ W,
                                           const float* __restrict__ a) {
    const int g = blockIdx.y, i0 = blockIdx.x * 64;
    __shared__ float sAT[64][68];      // [k][row], transposed, padded
    __shared__ float sW[64][64];       // [k][col]
    __shared__ float ssrc[64], sdst[64];
    const int tid = threadIdx.x, tx = tid & 15, ty = tid >> 4;
    float acc[4][4];
    #pragma unroll
    for (int r = 0; r < 4; r++)
        #pragma unroll
        for (int c = 0; c < 4; c++) acc[r][c] = 0.f;

    const float* Ab = atoms + ((size_t)(g * NN + i0)) * FIN;
    for (int ks = 0; ks < 2; ks++) {
        #pragma unroll
        for (int p = 0; p < 4; p++) {
            const int idx = p * 256 + tid;
            const int r = idx >> 4, q = idx & 15;
            const float4 va = *(const float4*)(Ab + (size_t)r * FIN + ks * 64 + q * 4);
            sAT[q * 4 + 0][r] = va.x; sAT[q * 4 + 1][r] = va.y;
            sAT[q * 4 + 2][r] = va.z; sAT[q * 4 + 3][r] = va.w;
        }
        #pragma unroll
        for (int p = 0; p < 4; p++) {
            const int idx = p * 256 + tid;
            const int k = idx >> 4, c = (idx & 15) * 4;
            *(float4*)&sW[k][c] = *(const float4*)(W + (size_t)(ks * 64 + k) * FF + c);
        }
        __syncthreads();
        #pragma unroll 8
        for (int k = 0; k < 64; k++) {
            const float4 a4 = *(const float4*)&sAT[k][ty * 4];
            const float4 b4 = *(const float4*)&sW[k][tx * 4];
            const float av[4] = {a4.x, a4.y, a4.z, a4.w};
            const float bv[4] = {b4.x, b4.y, b4.z, b4.w};
            #pragma unroll
            for (int r = 0; r < 4; r++)
                #pragma unroll
                for (int c = 0; c < 4; c++) acc[r][c] += av[r] * bv[c];
        }
        __syncthreads();
    }
    float a1v[4], a2v[4];
    #pragma unroll
    for (int j = 0; j < 4; j++) { a1v[j] = a[tx * 4 + j]; a2v[j] = a[FF + tx * 4 + j]; }
    #pragma unroll
    for (int r = 0; r < 4; r++) {
        float4 o;
        o.x = acc[r][0]; o.y = acc[r][1]; o.z = acc[r][2]; o.w = acc[r][3];
        *(float4*)(g_h + ((size_t)(g * NN + i0 + ty * 4 + r)) * FF + tx * 4) = o;
        float sr = acc[r][0] * a1v[0] + acc[r][1] * a1v[1] + acc[r][2] * a1v[2] + acc[r][3] * a1v[3];
        float sd = acc[r][0] * a2v[0] + acc[r][1] * a2v[1] + acc[r][2] * a2v[2] + acc[r][3] * a2v[3];
        #pragma unroll
        for (int off = 8; off > 0; off >>= 1) {
            sr += __shfl_xor_sync(0xFFFFFFFFu, sr, off);
            sd += __shfl_xor_sync(0xFFFFFFFFu, sd, off);
        }
        if (tx == 0) { ssrc[ty * 4 + r] = sr; sdst[ty * 4 + r] = sd; }
    }
    __syncthreads();
    if (tid < 64) {
        g_src[g * NN + i0 + tid] = ssrc[tid];
        g_dst[g * NN + i0 + tid] = sdst[tid];
    }
}

// ---------------- K3: blended rows, warp-per-row, no block barriers ----------------
__global__ __launch_bounds__(256) void k_blend(void) {
    const int g = blockIdx.y, rbase = blockIdx.x * 32;
    __shared__ __align__(16) unsigned short tbl[NN * DD];   // 16 KB
    __shared__ __align__(16) float accs[8][NN];             // 32 KB, one row per warp
    const int t = threadIdx.x, w = t >> 5, lane = t & 31;

    {
        const uint4* s4 = (const uint4*)(g_uniq + (size_t)g * NN * DD);
        uint4* d4 = (uint4*)tbl;
        #pragma unroll
        for (int p = 0; p < 4; p++) d4[p * 256 + t] = s4[p * 256 + t];
    }
    __syncthreads();

    float* A = accs[w];
    float4* A4 = (float4*)A;

    for (int rr = 0; rr < 4; rr++) {
        const int i = rbase + rr * 8 + w;
        #pragma unroll
        for (int q = 0; q < 8; q++) A4[q * 32 + lane] = make_float4(0.f, 0.f, 0.f, 0.f);
        __syncwarp();
        const unsigned short* ti = &tbl[i * DD];
        // A: 8 direct neighbors
        if (lane < 8) {
            const unsigned j = ti[lane];
            if (j != INVID) atomicAdd(&A[j], 1.0f);
        }
        // A^2: 64 paths (d,e)
        #pragma unroll
        for (int q = 0; q < 2; q++) {
            const int p = q * 32 + lane;
            const unsigned k1 = ti[p >> 3];
            if (k1 != INVID) {
                const unsigned j = tbl[k1 * DD + (p & 7)];
                if (j != INVID) atomicAdd(&A[j], 1.0f);
            }
        }
        // A^3: 512 paths (d,e,f)
        #pragma unroll
        for (int q = 0; q < 16; q++) {
            const int p = q * 32 + lane;
            const unsigned k1 = ti[p >> 6];
            if (k1 == INVID) continue;
            const unsigned m = tbl[k1 * DD + ((p >> 3) & 7)];
            if (m == INVID) continue;
            const unsigned j = tbl[m * DD + (p & 7)];
            if (j != INVID) atomicAdd(&A[j], 1.0f);
        }
        __syncwarp();
        // ---- softmax over the 1024 counts (warp-local, deterministic)
        float4 v[8];
        float mm = 0.f;   // counts are >= 0
        #pragma unroll
        for (int q = 0; q < 8; q++) {
            v[q] = A4[q * 32 + lane];
            mm = fmaxf(mm, fmaxf(fmaxf(v[q].x, v[q].y), fmaxf(v[q].z, v[q].w)));
        }
        #pragma unroll
        for (int off = 16; off > 0; off >>= 1) mm = fmaxf(mm, __shfl_xor_sync(0xFFFFFFFFu, mm, off));
        float ss = 0.f;
        #pragma unroll
        for (int q = 0; q < 8; q++) {
            v[q].x = __expf(v[q].x - mm); v[q].y = __expf(v[q].y - mm);
            v[q].z = __expf(v[q].z - mm); v[q].w = __expf(v[q].w - mm);
            ss += (v[q].x + v[q].y) + (v[q].z + v[q].w);
            A4[q * 32 + lane] = v[q];
        }
        #pragma unroll
        for (int off = 16; off > 0; off >>= 1) ss += __shfl_xor_sync(0xFFFFFFFFu, ss, off);
        const float Z = ss;
        __syncwarp();
        // ---- attention over unique neighbors (other entries exp -> exactly 0)
        {
            const unsigned j = (lane < 8) ? (unsigned)ti[lane] : INVID;
            const bool valid = (j != INVID);
            float x = -3.0e38f;
            if (valid) {
                const float vv = g_src[g * NN + i] + g_dst[g * NN + j];
                x = (vv > 0.f) ? vv : 0.2f * vv;       // leaky_relu
            }
            float me = x;
            #pragma unroll
            for (int off = 4; off > 0; off >>= 1) me = fmaxf(me, __shfl_xor_sync(0xFFFFFFFFu, me, off));
            const float ev = valid ? __expf(x - me) : 0.f;
            float Za = ev;
            #pragma unroll
            for (int off = 4; off > 0; off >>= 1) Za += __shfl_xor_sync(0xFFFFFFFFu, Za, off);
            // add pre-scaled so the final *0.5/Z yields 0.5*ev/Za
            if (valid) atomicAdd(&A[j], (ev / Za) * Z);
        }
        __syncwarp();
        const float sc = 0.5f / Z;
        float4* orow = (float4*)(g_blend + ((size_t)(g * NN + i)) * NN);
        #pragma unroll
        for (int q = 0; q < 8; q++) {
            float4 o = A4[q * 32 + lane];
            o.x *= sc; o.y *= sc; o.z *= sc; o.w *= sc;
            orow[q * 32 + lane] = o;
        }
        __syncwarp();
    }
}

// ---------------- K4: out = elu(blend @ h), 128x64 tile, 256 thr, 8x4/thread ----------------
// Pairs along M come free from LDS.128 of transposed A; B duplicated in smem so
// (b,b) pairs also come free. Inner loop: 16 FFMA2 + 4 LDS.128 per k.
__global__ __launch_bounds__(256) void k_gemm(float* __restrict__ out) {
    const int g = blockIdx.y, i0 = blockIdx.x * 128;
    __shared__ __align__(16) float As[2][16][132];   // [buf][k][row] transposed
    __shared__ __align__(16) float Bs[2][16][132];   // [buf][k][2*col] duplicated
    const int tid = threadIdx.x, tx = tid & 15, ty = tid >> 4;
    unsigned long long acc[4][4];
    #pragma unroll
    for (int m = 0; m < 4; m++)
        #pragma unroll
        for (int c = 0; c < 4; c++) acc[m][c] = 0ull;

    const float* Ab = g_blend + ((size_t)(g * NN + i0)) * NN;
    const float* Bb = g_h + (size_t)g * NN * FF;
    float4 ra[2], rb;

    // prologue: load tile 0
    #pragma unroll
    for (int p = 0; p < 2; p++) {
        const int idx = p * 256 + tid, r = idx >> 2, q = idx & 3;
        ra[p] = *(const float4*)(Ab + (size_t)r * NN + q * 4);
    }
    {
        const int r = tid >> 4, c = (tid & 15) * 4;
        rb = *(const float4*)(Bb + (size_t)r * FF + c);
    }
    #pragma unroll
    for (int p = 0; p < 2; p++) {
        const int idx = p * 256 + tid, r = idx >> 2, q = idx & 3;
        As[0][q * 4 + 0][r] = ra[p].x; As[0][q * 4 + 1][r] = ra[p].y;
        As[0][q * 4 + 2][r] = ra[p].z; As[0][q * 4 + 3][r] = ra[p].w;
    }
    {
        const int r = tid >> 4, c = (tid & 15) * 4;
        float4 d0, d1;
        d0.x = rb.x; d0.y = rb.x; d0.z = rb.y; d0.w = rb.y;
        d1.x = rb.z; d1.y = rb.z; d1.z = rb.w; d1.w = rb.w;
        *(float4*)&Bs[0][r][2 * c] = d0;
        *(float4*)&Bs[0][r][2 * c + 4] = d1;
    }
    __syncthreads();

    for (int ks = 0; ks < 64; ks++) {
        const int buf = ks & 1;
        if (ks < 63) {
            const int k0 = (ks + 1) * 16;
            #pragma unroll
            for (int p = 0; p < 2; p++) {
                const int idx = p * 256 + tid, r = idx >> 2, q = idx & 3;
                ra[p] = *(const float4*)(Ab + (size_t)r * NN + k0 + q * 4);
            }
            {
                const int r = tid >> 4, c = (tid & 15) * 4;
                rb = *(const float4*)(Bb + (size_t)(k0 + r) * FF + c);
            }
        }
        #pragma unroll
        for (int k = 0; k < 16; k++) {
            const ulonglong2 A01 = *(const ulonglong2*)&As[buf][k][ty * 8];
            const ulonglong2 A23 = *(const ulonglong2*)&As[buf][k][ty * 8 + 4];
            const ulonglong2 B01 = *(const ulonglong2*)&Bs[buf][k][tx * 8];
            const ulonglong2 B23 = *(const ulonglong2*)&Bs[buf][k][tx * 8 + 4];
            const unsigned long long ap[4] = {A01.x, A01.y, A23.x, A23.y};
            const unsigned long long bp[4] = {B01.x, B01.y, B23.x, B23.y};
            #pragma unroll
            for (int m = 0; m < 4; m++) {
                acc[m][0] = ffma2(ap[m], bp[0], acc[m][0]);
                acc[m][1] = ffma2(ap[m], bp[1], acc[m][1]);
                acc[m][2] = ffma2(ap[m], bp[2], acc[m][2]);
                acc[m][3] = ffma2(ap[m], bp[3], acc[m][3]);
            }
        }
        if (ks < 63) {
            const int nb = buf ^ 1;
            #pragma unroll
            for (int p = 0; p < 2; p++) {
                const int idx = p * 256 + tid, r = idx >> 2, q = idx & 3;
                As[nb][q * 4 + 0][r] = ra[p].x; As[nb][q * 4 + 1][r] = ra[p].y;
                As[nb][q * 4 + 2][r] = ra[p].z; As[nb][q * 4 + 3][r] = ra[p].w;
            }
            {
                const int r = tid >> 4, c = (tid & 15) * 4;
                float4 d0, d1;
                d0.x = rb.x; d0.y = rb.x; d0.z = rb.y; d0.w = rb.y;
                d1.x = rb.z; d1.y = rb.z; d1.z = rb.w; d1.w = rb.w;
                *(float4*)&Bs[nb][r][2 * c] = d0;
                *(float4*)&Bs[nb][r][2 * c + 4] = d1;
            }
        }
        __syncthreads();
    }
    // epilogue: acc[m][c] = (row ty*8+2m, row ty*8+2m+1) at col tx*4+c
    #pragma unroll
    for (int m = 0; m < 4; m++) {
        const float2 c0 = upk2(acc[m][0]), c1 = upk2(acc[m][1]);
        const float2 c2 = upk2(acc[m][2]), c3 = upk2(acc[m][3]);
        float4 e0, e1;
        e0.x = c0.x; e0.y = c1.x; e0.z = c2.x; e0.w = c3.x;   // even row
        e1.x = c0.y; e1.y = c1.y; e1.z = c2.y; e1.w = c3.y;   // odd row
        e0.x = (e0.x > 0.f) ? e0.x : (expf(e0.x) - 1.f);
        e0.y = (e0.y > 0.f) ? e0.y : (expf(e0.y) - 1.f);
        e0.z = (e0.z > 0.f) ? e0.z : (expf(e0.z) - 1.f);
        e0.w = (e0.w > 0.f) ? e0.w : (expf(e0.w) - 1.f);
        e1.x = (e1.x > 0.f) ? e1.x : (expf(e1.x) - 1.f);
        e1.y = (e1.y > 0.f) ? e1.y : (expf(e1.y) - 1.f);
        e1.z = (e1.z > 0.f) ? e1.z : (expf(e1.z) - 1.f);
        e1.w = (e1.w > 0.f) ? e1.w : (expf(e1.w) - 1.f);
        const int row = i0 + ty * 8 + 2 * m;
        *(float4*)(out + ((size_t)(g * NN + row)) * FF + tx * 4) = e0;
        *(float4*)(out + ((size_t)(g * NN + row + 1)) * FF + tx * 4) = e1;
    }
}

// ---------------- launcher ----------------
extern "C" void kernel_launch(void* const* d_in, const int* in_sizes, int n_in,
                              void* d_out, int out_size) {
    const float* atoms = (const float*)d_in[0];
    const int*   edges = (const int*)d_in[1];
    const float* W     = (const float*)d_in[2];
    const float* a     = (const float*)d_in[3];
    float* out = (float*)d_out;
    (void)in_sizes; (void)n_in; (void)out_size;

    k_h<<<dim3(16, GB), 256>>>(atoms, W, a);
    k_uniq<<<(GB * NN) / 256, 256>>>(edges);
    k_blend<<<dim3(32, GB), 256>>>();
    k_gemm<<<dim3(8, GB), 256>>>(out);
}

// round 11
// speedup vs baseline: 2.4809x; 1.8924x over previous
#include <cuda_runtime.h>
#include <cuda_bf16.h>
#include <cstdint>

#define GB 16
#define NN 1024
#define DD 8
#define FIN 128
#define FF 64
#define INVID 0xFFFFu

// ---------------- scratch (static device globals; no allocation) ----------------
static __device__ float g_src[GB*NN];
static __device__ float g_dst[GB*NN];
static __device__ __align__(16) unsigned short g_uniq[GB*NN*DD];
static __device__ __align__(16) unsigned short g_bh[(size_t)GB*NN*NN];   // blend hi bf16, 32 MB
static __device__ __align__(16) unsigned short g_bl[(size_t)GB*NN*NN];   // blend lo bf16, 32 MB
static __device__ __align__(16) unsigned short g_hTh[(size_t)GB*FF*NN];  // h^T hi bf16, 2 MB
static __device__ __align__(16) unsigned short g_hTl[(size_t)GB*FF*NN];  // h^T lo bf16, 2 MB

// ---------------- helpers ----------------
__device__ __forceinline__ uint32_t smem_u32(const void* p) {
    uint32_t a;
    asm("{ .reg .u64 t; cvta.to.shared.u64 t, %1; cvt.u32.u64 %0, t; }" : "=r"(a) : "l"(p));
    return a;
}
__device__ __forceinline__ void cp16(uint32_t dst, const void* src) {
    asm volatile("cp.async.cg.shared.global [%0], [%1], 16;" :: "r"(dst), "l"(src));
}
__device__ __forceinline__ void ldm4(uint32_t* r, uint32_t addr) {
    asm volatile("ldmatrix.sync.aligned.m8n8.x4.shared.b16 {%0,%1,%2,%3}, [%4];"
                 : "=r"(r[0]), "=r"(r[1]), "=r"(r[2]), "=r"(r[3]) : "r"(addr));
}
__device__ __forceinline__ void mma16816(float* c, const uint32_t* a,
                                         uint32_t b0, uint32_t b1) {
    asm volatile(
        "mma.sync.aligned.m16n8k16.row.col.f32.bf16.bf16.f32 "
        "{%0,%1,%2,%3}, {%4,%5,%6,%7}, {%8,%9}, {%0,%1,%2,%3};"
        : "+f"(c[0]), "+f"(c[1]), "+f"(c[2]), "+f"(c[3])
        : "r"(a[0]), "r"(a[1]), "r"(a[2]), "r"(a[3]), "r"(b0), "r"(b1));
}
__device__ __forceinline__ void bf16_split(float v, unsigned short& hi, unsigned short& lo) {
    __nv_bfloat16 h = __float2bfloat16(v);
    hi = __bfloat16_as_ushort(h);
    lo = __bfloat16_as_ushort(__float2bfloat16(v - __bfloat162float(h)));
}
#define SWZ(o) ((o) ^ (((o) >> 3) & 0x70))

// ---------------- K1: unique neighbor lists with 0xFFFF sentinels ----------------
__global__ __launch_bounds__(256) void k_uniq(const int* __restrict__ edges) {
    const int row = blockIdx.x * 256 + threadIdx.x;
    if (row >= GB * NN) return;
    const bool is64 = (edges[1] == 0) && (edges[3] == 0) && (edges[5] == 0) && (edges[7] == 0);
    unsigned e[DD];
    #pragma unroll
    for (int d = 0; d < DD; d++) {
        int w = is64 ? edges[((size_t)row * DD + d) * 2] : edges[row * DD + d];
        e[d] = (unsigned)w & (NN - 1);
    }
    unsigned u[DD];
    int c = 0;
    #pragma unroll
    for (int d = 0; d < DD; d++) {
        bool dup = false;
        #pragma unroll
        for (int t2 = 0; t2 < DD; t2++) if (t2 < c && u[t2] == e[d]) dup = true;
        if (!dup) u[c++] = e[d];
    }
    #pragma unroll
    for (int d = 0; d < DD; d++) if (d >= c) u[d] = INVID;
    uint4 pk;
    pk.x = u[0] | (u[1] << 16);
    pk.y = u[2] | (u[3] << 16);
    pk.z = u[4] | (u[5] << 16);
    pk.w = u[6] | (u[7] << 16);
    ((uint4*)g_uniq)[row] = pk;
}

// ---------------- K2: h = atoms @ W ; emit h^T (bf16 hi/lo) + src/dst ----------------
__global__ __launch_bounds__(256) void k_h(const float* __restrict__ atoms,
                                           const float* __restrict__ W,
                                           const float* __restrict__ a) {
    const int g = blockIdx.y, i0 = blockIdx.x * 64;
    __shared__ float sAT[64][68];
    __shared__ float sW[64][64];
    __shared__ float ssrc[64], sdst[64];
    const int tid = threadIdx.x, tx = tid & 15, ty = tid >> 4;
    float acc[4][4];
    #pragma unroll
    for (int r = 0; r < 4; r++)
        #pragma unroll
        for (int c = 0; c < 4; c++) acc[r][c] = 0.f;

    const float* Ab = atoms + ((size_t)(g * NN + i0)) * FIN;
    for (int ks = 0; ks < 2; ks++) {
        #pragma unroll
        for (int p = 0; p < 4; p++) {
            const int idx = p * 256 + tid;
            const int r = idx >> 4, q = idx & 15;
            const float4 va = *(const float4*)(Ab + (size_t)r * FIN + ks * 64 + q * 4);
            sAT[q * 4 + 0][r] = va.x; sAT[q * 4 + 1][r] = va.y;
            sAT[q * 4 + 2][r] = va.z; sAT[q * 4 + 3][r] = va.w;
        }
        #pragma unroll
        for (int p = 0; p < 4; p++) {
            const int idx = p * 256 + tid;
            const int k = idx >> 4, c = (idx & 15) * 4;
            *(float4*)&sW[k][c] = *(const float4*)(W + (size_t)(ks * 64 + k) * FF + c);
        }
        __syncthreads();
        #pragma unroll 8
        for (int k = 0; k < 64; k++) {
            const float4 a4 = *(const float4*)&sAT[k][ty * 4];
            const float4 b4 = *(const float4*)&sW[k][tx * 4];
            const float av[4] = {a4.x, a4.y, a4.z, a4.w};
            const float bv[4] = {b4.x, b4.y, b4.z, b4.w};
            #pragma unroll
            for (int r = 0; r < 4; r++)
                #pragma unroll
                for (int c = 0; c < 4; c++) acc[r][c] += av[r] * bv[c];
        }
        __syncthreads();
    }
    // stage transposed h into sAT: sAT[col][row]
    #pragma unroll
    for (int r = 0; r < 4; r++)
        #pragma unroll
        for (int c = 0; c < 4; c++) sAT[tx * 4 + c][ty * 4 + r] = acc[r][c];
    float a1v[4], a2v[4];
    #pragma unroll
    for (int j = 0; j < 4; j++) { a1v[j] = a[tx * 4 + j]; a2v[j] = a[FF + tx * 4 + j]; }
    #pragma unroll
    for (int r = 0; r < 4; r++) {
        float sr = acc[r][0] * a1v[0] + acc[r][1] * a1v[1] + acc[r][2] * a1v[2] + acc[r][3] * a1v[3];
        float sd = acc[r][0] * a2v[0] + acc[r][1] * a2v[1] + acc[r][2] * a2v[2] + acc[r][3] * a2v[3];
        #pragma unroll
        for (int off = 8; off > 0; off >>= 1) {
            sr += __shfl_xor_sync(0xFFFFFFFFu, sr, off);
            sd += __shfl_xor_sync(0xFFFFFFFFu, sd, off);
        }
        if (tx == 0) { ssrc[ty * 4 + r] = sr; sdst[ty * 4 + r] = sd; }
    }
    __syncthreads();
    {
        const int cc = tid >> 2, rb = (tid & 3) * 16;
        unsigned int hw[8], lw[8];
        #pragma unroll
        for (int j = 0; j < 8; j++) {
            unsigned short h0, l0, h1, l1;
            bf16_split(sAT[cc][rb + 2 * j], h0, l0);
            bf16_split(sAT[cc][rb + 2 * j + 1], h1, l1);
            hw[j] = (unsigned)h0 | ((unsigned)h1 << 16);
            lw[j] = (unsigned)l0 | ((unsigned)l1 << 16);
        }
        const size_t base = (size_t)g * FF * NN + (size_t)cc * NN + i0 + rb;
        uint4* dh = (uint4*)(g_hTh + base);
        uint4* dl = (uint4*)(g_hTl + base);
        dh[0] = make_uint4(hw[0], hw[1], hw[2], hw[3]);
        dh[1] = make_uint4(hw[4], hw[5], hw[6], hw[7]);
        dl[0] = make_uint4(lw[0], lw[1], lw[2], lw[3]);
        dl[1] = make_uint4(lw[4], lw[5], lw[6], lw[7]);
    }
    if (tid < 64) {
        g_src[g * NN + i0 + tid] = ssrc[tid];
        g_dst[g * NN + i0 + tid] = sdst[tid];
    }
}

// ---------------- K3: blended rows, warp-per-row; emit bf16 hi/lo ----------------
__global__ __launch_bounds__(256) void k_blend(void) {
    const int g = blockIdx.y, rbase = blockIdx.x * 32;
    __shared__ __align__(16) unsigned short tbl[NN * DD];
    __shared__ __align__(16) float accs[8][NN];
    const int t = threadIdx.x, w = t >> 5, lane = t & 31;

    {
        const uint4* s4 = (const uint4*)(g_uniq + (size_t)g * NN * DD);
        uint4* d4 = (uint4*)tbl;
        #pragma unroll
        for (int p = 0; p < 4; p++) d4[p * 256 + t] = s4[p * 256 + t];
    }
    __syncthreads();

    float* A = accs[w];
    float4* A4 = (float4*)A;

    for (int rr = 0; rr < 4; rr++) {
        const int i = rbase + rr * 8 + w;
        #pragma unroll
        for (int q = 0; q < 8; q++) A4[q * 32 + lane] = make_float4(0.f, 0.f, 0.f, 0.f);
        __syncwarp();
        const unsigned short* ti = &tbl[i * DD];
        if (lane < 8) {
            const unsigned j = ti[lane];
            if (j != INVID) atomicAdd(&A[j], 1.0f);
        }
        #pragma unroll
        for (int q = 0; q < 2; q++) {
            const int p = q * 32 + lane;
            const unsigned k1 = ti[p >> 3];
            if (k1 != INVID) {
                const unsigned j = tbl[k1 * DD + (p & 7)];
                if (j != INVID) atomicAdd(&A[j], 1.0f);
            }
        }
        #pragma unroll
        for (int q = 0; q < 16; q++) {
            const int p = q * 32 + lane;
            const unsigned k1 = ti[p >> 6];
            if (k1 == INVID) continue;
            const unsigned m = tbl[k1 * DD + ((p >> 3) & 7)];
            if (m == INVID) continue;
            const unsigned j = tbl[m * DD + (p & 7)];
            if (j != INVID) atomicAdd(&A[j], 1.0f);
        }
        __syncwarp();
        float4 v[8];
        float mm = 0.f;
        #pragma unroll
        for (int q = 0; q < 8; q++) {
            v[q] = A4[q * 32 + lane];
            mm = fmaxf(mm, fmaxf(fmaxf(v[q].x, v[q].y), fmaxf(v[q].z, v[q].w)));
        }
        #pragma unroll
        for (int off = 16; off > 0; off >>= 1) mm = fmaxf(mm, __shfl_xor_sync(0xFFFFFFFFu, mm, off));
        float ss = 0.f;
        #pragma unroll
        for (int q = 0; q < 8; q++) {
            v[q].x = __expf(v[q].x - mm); v[q].y = __expf(v[q].y - mm);
            v[q].z = __expf(v[q].z - mm); v[q].w = __expf(v[q].w - mm);
            ss += (v[q].x + v[q].y) + (v[q].z + v[q].w);
            A4[q * 32 + lane] = v[q];
        }
        #pragma unroll
        for (int off = 16; off > 0; off >>= 1) ss += __shfl_xor_sync(0xFFFFFFFFu, ss, off);
        const float Z = ss;
        __syncwarp();
        {
            const unsigned j = (lane < 8) ? (unsigned)ti[lane] : INVID;
            const bool valid = (j != INVID);
            float x = -3.0e38f;
            if (valid) {
                const float vv = g_src[g * NN + i] + g_dst[g * NN + j];
                x = (vv > 0.f) ? vv : 0.2f * vv;
            }
            float me = x;
            #pragma unroll
            for (int off = 4; off > 0; off >>= 1) me = fmaxf(me, __shfl_xor_sync(0xFFFFFFFFu, me, off));
            const float ev = valid ? __expf(x - me) : 0.f;
            float Za = ev;
            #pragma unroll
            for (int off = 4; off > 0; off >>= 1) Za += __shfl_xor_sync(0xFFFFFFFFu, Za, off);
            if (valid) atomicAdd(&A[j], (ev / Za) * Z);
        }
        __syncwarp();
        const float sc = 0.5f / Z;
        uint2* oh = (uint2*)(g_bh + ((size_t)(g * NN + i)) * NN);
        uint2* ol = (uint2*)(g_bl + ((size_t)(g * NN + i)) * NN);
        #pragma unroll
        for (int q = 0; q < 8; q++) {
            float4 o = A4[q * 32 + lane];
            o.x *= sc; o.y *= sc; o.z *= sc; o.w *= sc;
            unsigned short h0, l0, h1, l1, h2, l2, h3, l3;
            bf16_split(o.x, h0, l0); bf16_split(o.y, h1, l1);
            bf16_split(o.z, h2, l2); bf16_split(o.w, h3, l3);
            uint2 ph, pl;
            ph.x = (unsigned)h0 | ((unsigned)h1 << 16);
            ph.y = (unsigned)h2 | ((unsigned)h3 << 16);
            pl.x = (unsigned)l0 | ((unsigned)l1 << 16);
            pl.y = (unsigned)l2 | ((unsigned)l3 << 16);
            oh[q * 32 + lane] = ph;
            ol[q * 32 + lane] = pl;
        }
        __syncwarp();
    }
}

// ---------------- K4: out = elu(blend @ h) via mma.sync bf16, 2-term split ----------------
// M=128/N=64 tile per CTA, K chunks of 64, cp.async double buffer.
// smem per buf: Ah 16K | Al 16K | Bh 8K | Bl 8K = 48K; 2 bufs = 96K.
#define AOFF_L 16384
#define BOFF   32768
#define BOFF_L 40960
#define BUFS   49152
#define GEMM_SMEM (2 * BUFS)

__device__ __forceinline__ void load_chunk(uint32_t bs, int c, size_t arow, size_t brow, int tid) {
    #pragma unroll
    for (int p = 0; p < 4; p++) {
        const int idx = p * 256 + tid;
        const int r = idx >> 3, seg = idx & 7;
        const uint32_t d = bs + SWZ(r * 128 + seg * 16);
        const size_t off = arow + (size_t)r * NN + c * 64 + seg * 8;
        cp16(d, g_bh + off);
        cp16(d + AOFF_L, g_bl + off);
    }
    #pragma unroll
    for (int p = 0; p < 2; p++) {
        const int idx = p * 256 + tid;
        const int r = idx >> 3, seg = idx & 7;
        const uint32_t d = bs + BOFF + SWZ(r * 128 + seg * 16);
        const size_t off = brow + (size_t)r * NN + c * 64 + seg * 8;
        cp16(d, g_hTh + off);
        cp16(d + (BOFF_L - BOFF), g_hTl + off);
    }
    asm volatile("cp.async.commit_group;" ::: "memory");
}

__global__ __launch_bounds__(256) void k_gemm(float* __restrict__ out) {
    extern __shared__ __align__(1024) char smem[];
    const uint32_t sb = smem_u32(smem);
    const int tid = threadIdx.x, lane = tid & 31, wid = tid >> 5;
    const int wm = wid >> 1, wn = wid & 1;
    const int g = blockIdx.y, i0 = blockIdx.x * 128;

    const size_t arow = (size_t)(g * NN + i0) * NN;
    const size_t brow = (size_t)g * FF * NN;

    float acc[2][4][4];
    #pragma unroll
    for (int mt = 0; mt < 2; mt++)
        #pragma unroll
        for (int nt = 0; nt < 4; nt++)
            #pragma unroll
            for (int q = 0; q < 4; q++) acc[mt][nt][q] = 0.f;

    // ldmatrix per-thread base offsets (within a buffer)
    // A: row = wm*32 + mt*16 + (lane&15); k-half byte = (lane>>4)*16
    const int arow_l = wm * 32 + (lane & 15);
    const uint32_t aperm = ((unsigned)arow_l & 7) << 4;
    const uint32_t abase = (unsigned)arow_l * 128 + ((lane >> 4) * 16);
    // B: n = wn*32 + nt2*16 + (lane&7) + ((lane>>4)&1)*8; k-half byte = ((lane>>3)&1)*16
    const int brow_l = wn * 32 + (lane & 7) + ((lane >> 4) & 1) * 8;
    const uint32_t bperm = ((unsigned)brow_l & 7) << 4;
    const uint32_t bbase = (unsigned)brow_l * 128 + (((lane >> 3) & 1) * 16);

    // prologue: chunks 0 and 1
    load_chunk(sb, 0, arow, brow, tid);
    load_chunk(sb + BUFS, 1, arow, brow, tid);
    asm volatile("cp.async.wait_group 1;" ::: "memory");
    __syncthreads();

    for (int c = 0; c < 16; c++) {
        const uint32_t bs = sb + (c & 1) * BUFS;
        #pragma unroll
        for (int ks = 0; ks < 4; ks++) {
            const uint32_t kb = ks * 32;  // 16 elems = 32 bytes
            uint32_t ah[2][4], al[2][4];
            #pragma unroll
            for (int mt = 0; mt < 2; mt++) {
                const uint32_t ad = bs + abase + mt * 16 * 128 + ((kb ^ aperm) & 0x70) + (kb & ~0x70u);
                // simpler exact: offset = row*128 + ((kb + khalf) ^ perm) ; khalf already in abase
                const uint32_t addr = bs + (unsigned)(arow_l + mt * 16) * 128
                                     + (((kb + ((lane >> 4) * 16)) ^ ((((unsigned)(arow_l + mt * 16)) & 7) << 4)));
                (void)ad;
                ldm4(ah[mt], addr);
                ldm4(al[mt], addr + AOFF_L);
            }
            uint32_t bh[2][4], bl[2][4];
            #pragma unroll
            for (int nt2 = 0; nt2 < 2; nt2++) {
                const uint32_t addr = bs + BOFF + (unsigned)(brow_l + nt2 * 16) * 128
                                     + (((kb + (((lane >> 3) & 1) * 16)) ^ ((((unsigned)(brow_l + nt2 * 16)) & 7) << 4)));
                ldm4(bh[nt2], addr);
                ldm4(bl[nt2], addr + (BOFF_L - BOFF));
            }
            #pragma unroll
            for (int mt = 0; mt < 2; mt++)
                #pragma unroll
                for (int nt = 0; nt < 4; nt++) {
                    const int nt2 = nt >> 1, s = (nt & 1) * 2;
                    mma16816(acc[mt][nt], ah[mt], bh[nt2][s], bh[nt2][s + 1]);
                    mma16816(acc[mt][nt], ah[mt], bl[nt2][s], bl[nt2][s + 1]);
                    mma16816(acc[mt][nt], al[mt], bh[nt2][s], bh[nt2][s + 1]);
                }
        }
        __syncthreads();
        if (c + 2 < 16) {
            load_chunk(bs, c + 2, arow, brow, tid);
            asm volatile("cp.async.wait_group 1;" ::: "memory");
        } else {
            asm volatile("cp.async.wait_group 0;" ::: "memory");
        }
        __syncthreads();
    }

    // epilogue: ELU + store (c0,c1 -> row g4; c2,c3 -> row g4+8)
    const int g4 = lane >> 2, tig = lane & 3;
    #pragma unroll
    for (int mt = 0; mt < 2; mt++)
        #pragma unroll
        for (int nt = 0; nt < 4; nt++) {
            const int col = wn * 32 + nt * 8 + tig * 2;
            const int r0 = i0 + wm * 32 + mt * 16 + g4;
            float2 v0, v1;
            v0.x = acc[mt][nt][0]; v0.y = acc[mt][nt][1];
            v1.x = acc[mt][nt][2]; v1.y = acc[mt][nt][3];
            v0.x = (v0.x > 0.f) ? v0.x : (expf(v0.x) - 1.f);
            v0.y = (v0.y > 0.f) ? v0.y : (expf(v0.y) - 1.f);
            v1.x = (v1.x > 0.f) ? v1.x : (expf(v1.x) - 1.f);
            v1.y = (v1.y > 0.f) ? v1.y : (expf(v1.y) - 1.f);
            *(float2*)(out + ((size_t)(g * NN + r0)) * FF + col) = v0;
            *(float2*)(out + ((size_t)(g * NN + r0 + 8)) * FF + col) = v1;
        }
}

// ---------------- launcher ----------------
extern "C" void kernel_launch(void* const* d_in, const int* in_sizes, int n_in,
                              void* d_out, int out_size) {
    const float* atoms = (const float*)d_in[0];
    const int*   edges = (const int*)d_in[1];
    const float* W     = (const float*)d_in[2];
    const float* a     = (const float*)d_in[3];
    float* out = (float*)d_out;
    (void)in_sizes; (void)n_in; (void)out_size;

    cudaFuncSetAttribute(k_gemm, cudaFuncAttributeMaxDynamicSharedMemorySize, GEMM_SMEM);
    k_h<<<dim3(16, GB), 256>>>(atoms, W, a);
    k_uniq<<<(GB * NN) / 256, 256>>>(edges);
    k_blend<<<dim3(32, GB), 256>>>();
    k_gemm<<<dim3(8, GB), 256, GEMM_SMEM>>>(out);
}